// round 6
// baseline (speedup 1.0000x reference)
#include <cuda_runtime.h>
#include <cstddef>

// ---------------------------------------------------------------------------
// StyleGAN2 block: two mod/demod 3x3 convs + leaky relu + 1x1 RGB conv.
// B=8, CIN=COUT=256, H=W=128, LAT=512.
// Strategy: fold style into weights per batch at SMEM load; precompute 1/sigma;
// direct conv with f32x2 packed FMAs (2 FMAs per fma-pipe issue on sm_103a).
// ---------------------------------------------------------------------------

#define BATCH 8
#define CH    256
#define HW    128
#define LAT   512

// scratch (device-global: no allocations allowed)
__device__ float g_mid[(size_t)BATCH * CH * HW * HW];   // conv1 output, 134MB
__device__ float g_s1[BATCH * CH];
__device__ float g_s2[BATCH * CH];
__device__ float g_s3[BATCH * CH];
__device__ float g_r1[BATCH * CH];   // 1/sigma for conv1
__device__ float g_r2[BATCH * CH];   // 1/sigma for conv2

// ---------------- f32x2 helpers (sm_100+) ----------------
__device__ __forceinline__ unsigned long long pack2(float lo, float hi) {
    unsigned long long d;
    asm("mov.b64 %0, {%1, %2};" : "=l"(d) : "f"(lo), "f"(hi));
    return d;
}
__device__ __forceinline__ void unpack2(unsigned long long v, float& lo, float& hi) {
    asm("mov.b64 {%0, %1}, %2;" : "=f"(lo), "=f"(hi) : "l"(v));
}
__device__ __forceinline__ unsigned long long ffma2(unsigned long long a,
                                                    unsigned long long b,
                                                    unsigned long long c) {
    unsigned long long d;
    asm("fma.rn.f32x2 %0, %1, %2, %3;" : "=l"(d) : "l"(a), "l"(b), "l"(c));
    return d;
}

// ---------------- style affine: style[b,o] = w[b,:] . A_w[o,:] + A_b[o] -----
__global__ void styles_kernel(const float* __restrict__ wvec,
                              const float* __restrict__ Aw,
                              const float* __restrict__ Ab,
                              float* __restrict__ outp) {
    __shared__ float sw[LAT];
    const int b = blockIdx.x;
    const int tid = threadIdx.x;
    for (int k = tid; k < LAT; k += 256) sw[k] = __ldg(&wvec[b * LAT + k]);
    __syncthreads();
    const int o = tid;  // 256 threads
    float acc = 0.f;
    const float* ap = Aw + (size_t)o * LAT;
    #pragma unroll 4
    for (int k = 0; k < LAT; k++) acc += sw[k] * __ldg(&ap[k]);
    outp[b * CH + o] = acc + __ldg(&Ab[o]);
}

// ---------------- 1/sigma: rsig[b,o] = 1/sqrt(sum_i s^2[b,i]*sum_t W^2 + eps)
__global__ void rsigma_kernel(const float* __restrict__ style,
                              const float* __restrict__ W,   // [CH,CH,3,3]
                              float* __restrict__ rsig) {
    __shared__ float ss[CH];
    const int b = blockIdx.x;
    const int tid = threadIdx.x;
    {
        float s = style[b * CH + tid];
        ss[tid] = s * s;
    }
    __syncthreads();
    const int o = tid;
    float acc = 0.f;
    const float* wp = W + (size_t)o * CH * 9;
    for (int i = 0; i < CH; i++) {
        float wq = 0.f;
        #pragma unroll
        for (int t = 0; t < 9; t++) { float wv = __ldg(&wp[i * 9 + t]); wq += wv * wv; }
        acc += ss[i] * wq;
    }
    rsig[b * CH + o] = 1.0f / sqrtf(acc + 1e-8f);
}

// ---------------- fused mod/demod 3x3 conv + noise + bias + leaky relu ------
// CTA: 64 out-channels x (16 rows x 32 cols) pixel tile. 512 threads.
// Thread: 8 oc x 8 px (4 f32x2 pairs). Cin chunked by 8.
#define CK       8
#define IN_PITCH 35   // 34 used cols, odd pitch -> conflict-free LDS in-warp
#define SM_IN_FLOATS (CK * 18 * IN_PITCH)              // 5040 floats = 20160 B
#define SM_W_OFF     (SM_IN_FLOATS * 4)                // byte offset of weights
#define CONV_SMEM    (SM_W_OFF + CK * 9 * 64 * 8)      // + 36864 B = 57024 B

__global__ __launch_bounds__(512, 1)
void conv3x3_mod_kernel(const float* __restrict__ in,
                        const float* __restrict__ wgt,    // [CH,CH,3,3]
                        const float* __restrict__ style,  // [B,CH] (input ch)
                        const float* __restrict__ rsig,   // [B,CH] (out ch)
                        const float* __restrict__ bias,   // [CH]
                        const float* __restrict__ ns,     // [1]
                        const float* __restrict__ noise,  // [B,1,H,W]
                        float* __restrict__ outp) {
    extern __shared__ unsigned char smraw[];
    float*  s_in = (float*)smraw;                      // [CK][18][IN_PITCH]
    float2* s_w  = (float2*)(smraw + SM_W_OFF);        // [CK][9][64] (dup lanes)

    const int tid = threadIdx.x;
    const int og  = tid >> 6;        // 0..7  (oc group; constant per warp)
    const int pg  = tid & 63;        // pixel slot
    const int r   = pg >> 2;         // 0..15 row in tile
    const int cg  = pg & 3;          // 0..3 col group (8 px each)

    const int tilex = blockIdx.x;    // 0..3  (32-col tiles)
    const int tiley = blockIdx.y;    // 0..7  (16-row tiles)
    const int b     = blockIdx.z >> 2;
    const int ocb   = blockIdx.z & 3;

    const int y  = tiley * 16 + r;
    const int x0 = tilex * 32 + cg * 8;

    unsigned long long acc[8][4];
    #pragma unroll
    for (int j = 0; j < 8; j++)
        #pragma unroll
        for (int k = 0; k < 4; k++) acc[j][k] = 0ull;

    const float* style_b = style + b * CH;

    for (int c0 = 0; c0 < CH; c0 += CK) {
        // ---- stage weights (style-modulated, lane-duplicated) ----
        #pragma unroll
        for (int e = tid; e < 64 * CK * 9; e += 512) {
            int o    = e / (CK * 9);
            int remn = e - o * (CK * 9);
            int ci   = remn / 9;
            int tap  = remn - ci * 9;
            float v = __ldg(&wgt[((size_t)(ocb * 64 + o) * CH + (c0 + ci)) * 9 + tap])
                      * style_b[c0 + ci];
            s_w[(ci * 9 + tap) * 64 + o] = make_float2(v, v);
        }
        // ---- stage input slab (18 rows x 34 cols x CK, zero-padded) ----
        #pragma unroll
        for (int e = tid; e < CK * 18 * 34; e += 512) {
            int ci   = e / (18 * 34);
            int remn = e - ci * (18 * 34);
            int iy   = remn / 34;
            int ix   = remn - iy * 34;
            int gy = tiley * 16 - 1 + iy;
            int gx = tilex * 32 - 1 + ix;
            float v = 0.f;
            if ((unsigned)gy < (unsigned)HW && (unsigned)gx < (unsigned)HW)
                v = __ldg(&in[((size_t)(b * CH + c0 + ci) << 14) + (gy << 7) + gx]);
            s_in[(ci * 18 + iy) * IN_PITCH + ix] = v;
        }
        __syncthreads();

        // ---- accumulate ----
        #pragma unroll 1
        for (int ci = 0; ci < CK; ci++) {
            #pragma unroll
            for (int ky = 0; ky < 3; ky++) {
                const float* rowp = &s_in[(ci * 18 + r + ky) * IN_PITCH + cg * 8];
                float xr[10];
                #pragma unroll
                for (int m = 0; m < 10; m++) xr[m] = rowp[m];
                unsigned long long ev[5], od[4];
                #pragma unroll
                for (int k2 = 0; k2 < 5; k2++) ev[k2] = pack2(xr[2*k2], xr[2*k2+1]);
                #pragma unroll
                for (int k2 = 0; k2 < 4; k2++) od[k2] = pack2(xr[2*k2+1], xr[2*k2+2]);
                const unsigned long long* wb =
                    (const unsigned long long*)&s_w[(ci * 9 + ky * 3) * 64 + og * 8];
                #pragma unroll
                for (int j = 0; j < 8; j++) {
                    unsigned long long w0 = wb[j];          // tap kx=0
                    unsigned long long w1 = wb[64 + j];     // tap kx=1
                    unsigned long long w2 = wb[128 + j];     // tap kx=2
                    #pragma unroll
                    for (int k = 0; k < 4; k++) {
                        acc[j][k] = ffma2(ev[k],     w0, acc[j][k]);
                        acc[j][k] = ffma2(od[k],     w1, acc[j][k]);
                        acc[j][k] = ffma2(ev[k + 1], w2, acc[j][k]);
                    }
                }
            }
        }
        __syncthreads();
    }

    // ---- epilogue: demod, noise, bias, leaky relu ----
    const float nsv = ns[0];
    float nz[8];
    {
        const float* np = noise + ((size_t)b << 14) + (y << 7) + x0;
        #pragma unroll
        for (int k = 0; k < 4; k++) {
            float2 t = *(const float2*)(np + 2 * k);
            nz[2*k] = t.x; nz[2*k+1] = t.y;
        }
    }
    #pragma unroll
    for (int j = 0; j < 8; j++) {
        const int oc = ocb * 64 + og * 8 + j;
        const float rs = rsig[b * CH + oc];
        const float bj = bias[oc];
        float* op = outp + ((size_t)(b * CH + oc) << 14) + (y << 7) + x0;
        #pragma unroll
        for (int k = 0; k < 4; k++) {
            float v0, v1;
            unpack2(acc[j][k], v0, v1);
            v0 = v0 * rs + nsv * nz[2*k]     + bj;
            v1 = v1 * rs + nsv * nz[2*k + 1] + bj;
            v0 = (v0 > 0.f) ? v0 : 0.2f * v0;
            v1 = (v1 > 0.f) ? v1 : 0.2f * v1;
            *(float2*)(op + 2 * k) = make_float2(v0, v1);
        }
    }
}

// ---------------- RGB 1x1 modulated conv (no demod) ------------------------
__global__ void rgb_kernel(const float* __restrict__ out2,
                           const float* __restrict__ W3,      // [3,CH]
                           const float* __restrict__ style3,  // [B,CH]
                           float* __restrict__ rgb) {
    __shared__ float cf[3][CH];
    const int y = blockIdx.x;
    const int b = blockIdx.y;
    const int tid = threadIdx.x;   // 128 threads = x
    for (int e = tid; e < 3 * CH; e += 128) {
        int rr = e >> 8;
        int o  = e & 255;
        cf[rr][o] = __ldg(&W3[rr * CH + o]) * style3[b * CH + o];
    }
    __syncthreads();
    const int x = tid;
    float a0 = 0.f, a1 = 0.f, a2 = 0.f;
    const float* base = out2 + ((size_t)(b * CH) << 14) + (y << 7) + x;
    #pragma unroll 4
    for (int o = 0; o < CH; o++) {
        float v = base[(size_t)o << 14];
        a0 += cf[0][o] * v;
        a1 += cf[1][o] * v;
        a2 += cf[2][o] * v;
    }
    const size_t px = ((size_t)y << 7) + x;
    rgb[((size_t)(b * 3 + 0) << 14) + px] = a0;
    rgb[((size_t)(b * 3 + 1) << 14) + px] = a1;
    rgb[((size_t)(b * 3 + 2) << 14) + px] = a2;
}

// ---------------------------------------------------------------------------
extern "C" void kernel_launch(void* const* d_in, const int* in_sizes, int n_in,
                              void* d_out, int out_size) {
    (void)in_sizes; (void)n_in; (void)out_size;
    const float* fm     = (const float*)d_in[0];
    const float* wv     = (const float*)d_in[1];
    const float* noise1 = (const float*)d_in[2];
    const float* noise2 = (const float*)d_in[3];
    const float* A1w    = (const float*)d_in[4];
    const float* A1b    = (const float*)d_in[5];
    const float* A2w    = (const float*)d_in[6];
    const float* A2b    = (const float*)d_in[7];
    const float* A3w    = (const float*)d_in[8];
    const float* A3b    = (const float*)d_in[9];
    const float* W1     = (const float*)d_in[10];
    const float* W2     = (const float*)d_in[11];
    const float* W3     = (const float*)d_in[12];
    const float* ns1    = (const float*)d_in[13];
    const float* ns2    = (const float*)d_in[14];
    const float* b1     = (const float*)d_in[15];
    const float* b2     = (const float*)d_in[16];

    float* out = (float*)d_out;                                   // [8,256,128,128]
    float* rgb = out + (size_t)BATCH * CH * HW * HW;              // [8,3,128,128]

    void *p_mid, *p_s1, *p_s2, *p_s3, *p_r1, *p_r2;
    cudaGetSymbolAddress(&p_mid, g_mid);
    cudaGetSymbolAddress(&p_s1, g_s1);
    cudaGetSymbolAddress(&p_s2, g_s2);
    cudaGetSymbolAddress(&p_s3, g_s3);
    cudaGetSymbolAddress(&p_r1, g_r1);
    cudaGetSymbolAddress(&p_r2, g_r2);
    float* mid = (float*)p_mid;
    float* s1 = (float*)p_s1; float* s2 = (float*)p_s2; float* s3 = (float*)p_s3;
    float* r1 = (float*)p_r1; float* r2 = (float*)p_r2;

    cudaFuncSetAttribute(conv3x3_mod_kernel,
                         cudaFuncAttributeMaxDynamicSharedMemorySize, CONV_SMEM);

    styles_kernel<<<BATCH, 256>>>(wv, A1w, A1b, s1);
    styles_kernel<<<BATCH, 256>>>(wv, A2w, A2b, s2);
    styles_kernel<<<BATCH, 256>>>(wv, A3w, A3b, s3);
    rsigma_kernel<<<BATCH, 256>>>(s1, W1, r1);
    rsigma_kernel<<<BATCH, 256>>>(s2, W2, r2);

    dim3 cgrid(4, 8, BATCH * 4);
    conv3x3_mod_kernel<<<cgrid, 512, CONV_SMEM>>>(fm,  W1, s1, r1, b1, ns1, noise1, mid);
    conv3x3_mod_kernel<<<cgrid, 512, CONV_SMEM>>>(mid, W2, s2, r2, b2, ns2, noise2, out);

    rgb_kernel<<<dim3(HW, BATCH), 128>>>(out, W3, s3, rgb);
}

// round 7
// speedup vs baseline: 1.0889x; 1.0889x over previous
#include <cuda_runtime.h>
#include <cstddef>

// ---------------------------------------------------------------------------
// StyleGAN2 block: two mod/demod 3x3 convs + leaky relu + 1x1 RGB conv.
// B=8, CIN=COUT=256, H=W=128, LAT=512.
// R7: 4oc x 8px per thread (no spills), double-buffered SMEM with register
// prefetch (one barrier/chunk), factored sigma, coalesced style GEMVs.
// ---------------------------------------------------------------------------

#define BATCH 8
#define CH    256
#define HW    128
#define LAT   512

// scratch (device-global: no allocations allowed)
__device__ float g_mid[(size_t)BATCH * CH * HW * HW];   // conv1 output, 134MB
__device__ float g_s1[BATCH * CH];
__device__ float g_s2[BATCH * CH];
__device__ float g_s3[BATCH * CH];
__device__ float g_r1[BATCH * CH];
__device__ float g_r2[BATCH * CH];
__device__ float g_wq1[CH * CH];    // sum_t W1[o,i,t]^2
__device__ float g_wq2[CH * CH];    // sum_t W2[o,i,t]^2

// ---------------- f32x2 helpers (sm_100+) ----------------
__device__ __forceinline__ unsigned long long pack2(float lo, float hi) {
    unsigned long long d;
    asm("mov.b64 %0, {%1, %2};" : "=l"(d) : "f"(lo), "f"(hi));
    return d;
}
__device__ __forceinline__ void unpack2(unsigned long long v, float& lo, float& hi) {
    asm("mov.b64 {%0, %1}, %2;" : "=f"(lo), "=f"(hi) : "l"(v));
}
__device__ __forceinline__ unsigned long long ffma2(unsigned long long a,
                                                    unsigned long long b,
                                                    unsigned long long c) {
    unsigned long long d;
    asm("fma.rn.f32x2 %0, %1, %2, %3;" : "=l"(d) : "l"(a), "l"(b), "l"(c));
    return d;
}
__device__ __forceinline__ float warp_sum(float v) {
    #pragma unroll
    for (int m = 16; m > 0; m >>= 1)
        v += __shfl_xor_sync(0xffffffffu, v, m);
    return v;
}

// ---------------- styles: style[b,o] = w[b,:] . A_w[o,:] + A_b[o] -----------
// warp per output row -> fully coalesced reads of Aw.
__global__ void styles_kernel(const float* __restrict__ wvec,
                              const float* __restrict__ Aw,
                              const float* __restrict__ Ab,
                              float* __restrict__ outp) {
    const int b    = blockIdx.y;
    const int wid  = threadIdx.x >> 5;
    const int lane = threadIdx.x & 31;
    const int o    = blockIdx.x * 8 + wid;
    const float* wp = wvec + b * LAT;
    const float* ap = Aw + (size_t)o * LAT;
    float acc = 0.f;
    #pragma unroll
    for (int it = 0; it < LAT / 32; it++) {
        int k = lane + 32 * it;
        acc += __ldg(&wp[k]) * __ldg(&ap[k]);
    }
    acc = warp_sum(acc);
    if (lane == 0) outp[b * CH + o] = acc + __ldg(&Ab[o]);
}

// ---------------- wq[o,i] = sum_t W[o,i,t]^2 (batch independent) ------------
__global__ void wsq_kernel(const float* __restrict__ W, float* __restrict__ wq) {
    const int oi = blockIdx.x * 256 + threadIdx.x;   // 0..65535
    const float* wp = W + (size_t)oi * 9;
    float s = 0.f;
    #pragma unroll
    for (int t = 0; t < 9; t++) { float v = __ldg(&wp[t]); s += v * v; }
    wq[oi] = s;
}

// ---------------- rsig[b,o] = rsqrt( sum_i s^2[b,i] * wq[o,i] + eps ) -------
__global__ void rsigma_kernel(const float* __restrict__ style,
                              const float* __restrict__ wq,
                              float* __restrict__ rsig) {
    __shared__ float ss[CH];
    const int b    = blockIdx.x;
    const int tid  = threadIdx.x;
    const int wid  = tid >> 5;
    const int lane = tid & 31;
    { float s = style[b * CH + tid]; ss[tid] = s * s; }
    __syncthreads();
    const int o0 = blockIdx.y * 32 + wid * 4;
    #pragma unroll
    for (int j = 0; j < 4; j++) {
        const int o = o0 + j;
        const float* qp = wq + (size_t)o * CH;
        float acc = 0.f;
        #pragma unroll
        for (int it = 0; it < CH / 32; it++) {
            int i = lane + 32 * it;
            acc += ss[i] * __ldg(&qp[i]);
        }
        acc = warp_sum(acc);
        if (lane == 0) rsig[b * CH + o] = rsqrtf(acc + 1e-8f);
    }
}

// ---------------- fused mod/demod 3x3 conv + noise + bias + leaky relu ------
// CTA: 32 out-channels x (16 rows x 32 cols) pixel tile. 512 threads.
// Thread: 4 oc x 8 px (16 f32x2 accumulators). Cin chunked by 8.
// Double-buffered SMEM; register prefetch of next chunk overlapped with FMAs.
#define CK        8
#define IN_PITCH  35   // 34 used cols; bank = (3r+8cg) mod 32 injective in-warp
#define IN_FLOATS (CK * 18 * IN_PITCH)               // 5040
#define W_ELEMS   (CK * 9 * 32)                      // 2304 float2 entries
#define IN_TOT    (CK * 18 * 34)                     // 4896 staged elems
#define W_TOT     (32 * CK * 9)                      // 2304 staged elems
#define SM_STYLE_OFF 0
#define SM_IN_OFF    1024                            // after 256-float style
#define SM_W_OFF     (SM_IN_OFF + 2 * IN_FLOATS * 4) // 1024 + 40320
#define CONV_SMEM    (SM_W_OFF + 2 * W_ELEMS * 8)    // + 36864 = 78208 B

__global__ __launch_bounds__(512, 1)
void conv3x3_mod_kernel(const float* __restrict__ in,
                        const float* __restrict__ wgt,    // [CH,CH,3,3]
                        const float* __restrict__ style,  // [B,CH] (input ch)
                        const float* __restrict__ rsig,   // [B,CH] (out ch)
                        const float* __restrict__ bias,   // [CH]
                        const float* __restrict__ ns,     // [1]
                        const float* __restrict__ noise,  // [B,1,H,W]
                        float* __restrict__ outp) {
    extern __shared__ unsigned char smraw[];
    float* s_style = (float*)(smraw + SM_STYLE_OFF);   // [256]
    float* s_in    = (float*)(smraw + SM_IN_OFF);      // [2][CK*18*IN_PITCH]
    float2* s_w    = (float2*)(smraw + SM_W_OFF);      // [2][CK*9*32]

    const int tid = threadIdx.x;
    const int og  = tid >> 6;        // 0..7  (oc quad; constant per warp)
    const int pg  = tid & 63;
    const int r   = pg >> 2;         // 0..15
    const int cg  = pg & 3;          // 0..3

    const int tilex = blockIdx.x;    // 0..3
    const int tiley = blockIdx.y;    // 0..7
    const int b     = blockIdx.z >> 3;
    const int ocb   = blockIdx.z & 7;   // 8 blocks of 32 oc

    const int y  = tiley * 16 + r;
    const int x0 = tilex * 32 + cg * 8;

    unsigned long long acc[4][4];
    #pragma unroll
    for (int j = 0; j < 4; j++)
        #pragma unroll
        for (int k = 0; k < 4; k++) acc[j][k] = 0ull;

    if (tid < CH) s_style[tid] = __ldg(&style[b * CH + tid]);

    float wpre[5];
    float ipre[10];

    // ---- prefetch chunk c0n into registers ----
    auto prefetch = [&](int c0n) {
        #pragma unroll
        for (int i = 0; i < 5; i++) {
            int e = tid + 512 * i;
            if (e < W_TOT) {
                int o = e / (CK * 9);
                int rem = e - o * (CK * 9);
                int ci = rem / 9;
                int tap = rem - ci * 9;
                wpre[i] = __ldg(&wgt[((size_t)(ocb * 32 + o) * CH + (c0n + ci)) * 9 + tap]);
            }
        }
        #pragma unroll
        for (int i = 0; i < 10; i++) {
            int e = tid + 512 * i;
            if (e < IN_TOT) {
                int ci  = e / (18 * 34);
                int rem = e - ci * (18 * 34);
                int iy  = rem / 34;
                int ix  = rem - iy * 34;
                int gy = tiley * 16 - 1 + iy;
                int gx = tilex * 32 - 1 + ix;
                float v = 0.f;
                if ((unsigned)gy < (unsigned)HW && (unsigned)gx < (unsigned)HW)
                    v = __ldg(&in[((size_t)(b * CH + c0n + ci) << 14) + (gy << 7) + gx]);
                ipre[i] = v;
            }
        }
    };
    // ---- store prefetched regs to smem buffer p (modulating weights) ----
    auto store_stage = [&](int c0n, int p) {
        float* sin_p = s_in + p * IN_FLOATS;
        float2* sw_p = s_w + p * W_ELEMS;
        #pragma unroll
        for (int i = 0; i < 5; i++) {
            int e = tid + 512 * i;
            if (e < W_TOT) {
                int o = e / (CK * 9);
                int rem = e - o * (CK * 9);
                int ci = rem / 9;
                int tap = rem - ci * 9;
                float v = wpre[i] * s_style[c0n + ci];
                sw_p[(ci * 9 + tap) * 32 + o] = make_float2(v, v);
            }
        }
        #pragma unroll
        for (int i = 0; i < 10; i++) {
            int e = tid + 512 * i;
            if (e < IN_TOT) {
                int ci  = e / (18 * 34);
                int rem = e - ci * (18 * 34);
                int iy  = rem / 34;
                int ix  = rem - iy * 34;
                sin_p[(ci * 18 + iy) * IN_PITCH + ix] = ipre[i];
            }
        }
    };

    prefetch(0);
    __syncthreads();            // s_style visible
    store_stage(0, 0);
    __syncthreads();            // buffer 0 ready

    for (int c = 0; c < CH / CK; c++) {
        const int p = c & 1;
        if (c + 1 < CH / CK) prefetch((c + 1) * CK);   // LDGs in flight

        // ---- compute from buffer p ----
        const float* sin_p = s_in + p * IN_FLOATS;
        const float2* sw_p = s_w + p * W_ELEMS;
        #pragma unroll 1
        for (int ci = 0; ci < CK; ci++) {
            #pragma unroll
            for (int ky = 0; ky < 3; ky++) {
                const float* rowp = &sin_p[(ci * 18 + r + ky) * IN_PITCH + cg * 8];
                float xr[10];
                #pragma unroll
                for (int m = 0; m < 10; m++) xr[m] = rowp[m];
                unsigned long long ev[5], od[4];
                #pragma unroll
                for (int k2 = 0; k2 < 5; k2++) ev[k2] = pack2(xr[2*k2], xr[2*k2+1]);
                #pragma unroll
                for (int k2 = 0; k2 < 4; k2++) od[k2] = pack2(xr[2*k2+1], xr[2*k2+2]);
                const unsigned long long* wrow =
                    (const unsigned long long*)&sw_p[(ci * 9 + ky * 3) * 32 + og * 4];
                #pragma unroll
                for (int j = 0; j < 4; j++) {
                    unsigned long long w0 = wrow[j];        // kx=0
                    unsigned long long w1 = wrow[32 + j];   // kx=1
                    unsigned long long w2 = wrow[64 + j];   // kx=2
                    #pragma unroll
                    for (int k = 0; k < 4; k++) {
                        acc[j][k] = ffma2(ev[k],     w0, acc[j][k]);
                        acc[j][k] = ffma2(od[k],     w1, acc[j][k]);
                        acc[j][k] = ffma2(ev[k + 1], w2, acc[j][k]);
                    }
                }
            }
        }

        if (c + 1 < CH / CK) store_stage((c + 1) * CK, 1 - p);
        __syncthreads();
    }

    // ---- epilogue: demod, noise, bias, leaky relu ----
    const float nsv = ns[0];
    float nz[8];
    {
        const float* np = noise + ((size_t)b << 14) + (y << 7) + x0;
        #pragma unroll
        for (int k = 0; k < 4; k++) {
            float2 t = *(const float2*)(np + 2 * k);
            nz[2*k] = t.x; nz[2*k+1] = t.y;
        }
    }
    #pragma unroll
    for (int j = 0; j < 4; j++) {
        const int oc = ocb * 32 + og * 4 + j;
        const float rs = rsig[b * CH + oc];
        const float bj = bias[oc];
        float* op = outp + ((size_t)(b * CH + oc) << 14) + (y << 7) + x0;
        #pragma unroll
        for (int k = 0; k < 4; k++) {
            float v0, v1;
            unpack2(acc[j][k], v0, v1);
            v0 = v0 * rs + nsv * nz[2*k]     + bj;
            v1 = v1 * rs + nsv * nz[2*k + 1] + bj;
            v0 = (v0 > 0.f) ? v0 : 0.2f * v0;
            v1 = (v1 > 0.f) ? v1 : 0.2f * v1;
            *(float2*)(op + 2 * k) = make_float2(v0, v1);
        }
    }
}

// ---------------- RGB 1x1 modulated conv (no demod) ------------------------
__global__ void rgb_kernel(const float* __restrict__ out2,
                           const float* __restrict__ W3,      // [3,CH]
                           const float* __restrict__ style3,  // [B,CH]
                           float* __restrict__ rgb) {
    __shared__ float cf[3][CH];
    const int y = blockIdx.x;
    const int b = blockIdx.y;
    const int tid = threadIdx.x;   // 128 threads = x
    for (int e = tid; e < 3 * CH; e += 128) {
        int rr = e >> 8;
        int o  = e & 255;
        cf[rr][o] = __ldg(&W3[rr * CH + o]) * style3[b * CH + o];
    }
    __syncthreads();
    const int x = tid;
    float a0 = 0.f, a1 = 0.f, a2 = 0.f;
    const float* base = out2 + ((size_t)(b * CH) << 14) + (y << 7) + x;
    #pragma unroll 8
    for (int o = 0; o < CH; o++) {
        float v = base[(size_t)o << 14];
        a0 += cf[0][o] * v;
        a1 += cf[1][o] * v;
        a2 += cf[2][o] * v;
    }
    const size_t px = ((size_t)y << 7) + x;
    rgb[((size_t)(b * 3 + 0) << 14) + px] = a0;
    rgb[((size_t)(b * 3 + 1) << 14) + px] = a1;
    rgb[((size_t)(b * 3 + 2) << 14) + px] = a2;
}

// ---------------------------------------------------------------------------
extern "C" void kernel_launch(void* const* d_in, const int* in_sizes, int n_in,
                              void* d_out, int out_size) {
    (void)in_sizes; (void)n_in; (void)out_size;
    const float* fm     = (const float*)d_in[0];
    const float* wv     = (const float*)d_in[1];
    const float* noise1 = (const float*)d_in[2];
    const float* noise2 = (const float*)d_in[3];
    const float* A1w    = (const float*)d_in[4];
    const float* A1b    = (const float*)d_in[5];
    const float* A2w    = (const float*)d_in[6];
    const float* A2b    = (const float*)d_in[7];
    const float* A3w    = (const float*)d_in[8];
    const float* A3b    = (const float*)d_in[9];
    const float* W1     = (const float*)d_in[10];
    const float* W2     = (const float*)d_in[11];
    const float* W3     = (const float*)d_in[12];
    const float* ns1    = (const float*)d_in[13];
    const float* ns2    = (const float*)d_in[14];
    const float* b1     = (const float*)d_in[15];
    const float* b2     = (const float*)d_in[16];

    float* out = (float*)d_out;                                   // [8,256,128,128]
    float* rgb = out + (size_t)BATCH * CH * HW * HW;              // [8,3,128,128]

    void *p_mid, *p_s1, *p_s2, *p_s3, *p_r1, *p_r2, *p_q1, *p_q2;
    cudaGetSymbolAddress(&p_mid, g_mid);
    cudaGetSymbolAddress(&p_s1, g_s1);
    cudaGetSymbolAddress(&p_s2, g_s2);
    cudaGetSymbolAddress(&p_s3, g_s3);
    cudaGetSymbolAddress(&p_r1, g_r1);
    cudaGetSymbolAddress(&p_r2, g_r2);
    cudaGetSymbolAddress(&p_q1, g_wq1);
    cudaGetSymbolAddress(&p_q2, g_wq2);
    float* mid = (float*)p_mid;
    float* s1 = (float*)p_s1; float* s2 = (float*)p_s2; float* s3 = (float*)p_s3;
    float* r1 = (float*)p_r1; float* r2 = (float*)p_r2;
    float* q1 = (float*)p_q1; float* q2 = (float*)p_q2;

    cudaFuncSetAttribute(conv3x3_mod_kernel,
                         cudaFuncAttributeMaxDynamicSharedMemorySize, CONV_SMEM);

    styles_kernel<<<dim3(CH / 8, BATCH), 256>>>(wv, A1w, A1b, s1);
    styles_kernel<<<dim3(CH / 8, BATCH), 256>>>(wv, A2w, A2b, s2);
    styles_kernel<<<dim3(CH / 8, BATCH), 256>>>(wv, A3w, A3b, s3);
    wsq_kernel<<<CH * CH / 256, 256>>>(W1, q1);
    wsq_kernel<<<CH * CH / 256, 256>>>(W2, q2);
    rsigma_kernel<<<dim3(BATCH, CH / 32), 256>>>(s1, q1, r1);
    rsigma_kernel<<<dim3(BATCH, CH / 32), 256>>>(s2, q2, r2);

    dim3 cgrid(4, 8, BATCH * 8);
    conv3x3_mod_kernel<<<cgrid, 512, CONV_SMEM>>>(fm,  W1, s1, r1, b1, ns1, noise1, mid);
    conv3x3_mod_kernel<<<cgrid, 512, CONV_SMEM>>>(mid, W2, s2, r2, b2, ns2, noise2, out);

    rgb_kernel<<<dim3(HW, BATCH), 128>>>(out, W3, s3, rgb);
}

// round 8
// speedup vs baseline: 1.1274x; 1.0353x over previous
#include <cuda_runtime.h>
#include <cstddef>
#include <cstdint>

// ---------------------------------------------------------------------------
// StyleGAN2 block: two mod/demod 3x3 convs + leaky relu + 1x1 RGB conv.
// B=8, CIN=COUT=256, H=W=128, LAT=512.
// R8: 8oc x 8px per thread (64 oc / CTA); weights pre-rearranged for LDS.128
// broadcast + staged via cp.async (no registers); style folded into the input
// slab at staging; double-buffered smem; f32x2 packed FMAs.
// ---------------------------------------------------------------------------

#define BATCH 8
#define CH    256
#define HW    128
#define LAT   512

// scratch (device-global: no allocations allowed)
__device__ float g_mid[(size_t)BATCH * CH * HW * HW];   // conv1 output, 134MB
__device__ float g_s1[BATCH * CH];
__device__ float g_s2[BATCH * CH];
__device__ float g_s3[BATCH * CH];
__device__ float g_r1[BATCH * CH];
__device__ float g_r2[BATCH * CH];
__device__ float g_wq1[CH * CH];
__device__ float g_wq2[CH * CH];
// rearranged duplicated weights: [ocb(4)][chunk(32)][ci(8)][ky(3)][og(8)][jp(4)][slot(8)] float2
#define WR_F2 ((size_t)4 * 32 * 8 * 3 * 8 * 4 * 8)
__device__ float2 g_wr1[WR_F2];
__device__ float2 g_wr2[WR_F2];

// ---------------- f32x2 helpers (sm_100+) ----------------
__device__ __forceinline__ unsigned long long pack2(float lo, float hi) {
    unsigned long long d;
    asm("mov.b64 %0, {%1, %2};" : "=l"(d) : "f"(lo), "f"(hi));
    return d;
}
__device__ __forceinline__ void unpack2(unsigned long long v, float& lo, float& hi) {
    asm("mov.b64 {%0, %1}, %2;" : "=f"(lo), "=f"(hi) : "l"(v));
}
__device__ __forceinline__ unsigned long long ffma2(unsigned long long a,
                                                    unsigned long long b,
                                                    unsigned long long c) {
    unsigned long long d;
    asm("fma.rn.f32x2 %0, %1, %2, %3;" : "=l"(d) : "l"(a), "l"(b), "l"(c));
    return d;
}
__device__ __forceinline__ float warp_sum(float v) {
    #pragma unroll
    for (int m = 16; m > 0; m >>= 1)
        v += __shfl_xor_sync(0xffffffffu, v, m);
    return v;
}
__device__ __forceinline__ void cp_async16(void* smem, const void* gmem) {
    uint32_t s = (uint32_t)__cvta_generic_to_shared(smem);
    asm volatile("cp.async.cg.shared.global [%0], [%1], 16;" :: "r"(s), "l"(gmem));
}
#define CP_COMMIT() asm volatile("cp.async.commit_group;" ::: "memory")
#define CP_WAIT0()  asm volatile("cp.async.wait_group 0;" ::: "memory")

// ---------------- styles: style[b,o] = w[b,:] . A_w[o,:] + A_b[o] -----------
__global__ void styles_kernel(const float* __restrict__ wvec,
                              const float* __restrict__ Aw,
                              const float* __restrict__ Ab,
                              float* __restrict__ outp) {
    const int b    = blockIdx.y;
    const int wid  = threadIdx.x >> 5;
    const int lane = threadIdx.x & 31;
    const int o    = blockIdx.x * 8 + wid;
    const float* wp = wvec + b * LAT;
    const float* ap = Aw + (size_t)o * LAT;
    float acc = 0.f;
    #pragma unroll
    for (int it = 0; it < LAT / 32; it++) {
        int k = lane + 32 * it;
        acc += __ldg(&wp[k]) * __ldg(&ap[k]);
    }
    acc = warp_sum(acc);
    if (lane == 0) outp[b * CH + o] = acc + __ldg(&Ab[o]);
}

// ---------------- wq[o,i] = sum_t W[o,i,t]^2 (batch independent) ------------
__global__ void wsq_kernel(const float* __restrict__ W, float* __restrict__ wq) {
    const int oi = blockIdx.x * 256 + threadIdx.x;
    const float* wp = W + (size_t)oi * 9;
    float s = 0.f;
    #pragma unroll
    for (int t = 0; t < 9; t++) { float v = __ldg(&wp[t]); s += v * v; }
    wq[oi] = s;
}

// ---------------- rsig[b,o] = rsqrt( sum_i s^2[b,i] * wq[o,i] + eps ) -------
__global__ void rsigma_kernel(const float* __restrict__ style,
                              const float* __restrict__ wq,
                              float* __restrict__ rsig) {
    __shared__ float ss[CH];
    const int b    = blockIdx.x;
    const int tid  = threadIdx.x;
    const int wid  = tid >> 5;
    const int lane = tid & 31;
    { float s = style[b * CH + tid]; ss[tid] = s * s; }
    __syncthreads();
    const int o0 = blockIdx.y * 32 + wid * 4;
    #pragma unroll
    for (int j = 0; j < 4; j++) {
        const int o = o0 + j;
        const float* qp = wq + (size_t)o * CH;
        float acc = 0.f;
        #pragma unroll
        for (int it = 0; it < CH / 32; it++) {
            int i = lane + 32 * it;
            acc += ss[i] * __ldg(&qp[i]);
        }
        acc = warp_sum(acc);
        if (lane == 0) rsig[b * CH + o] = rsqrtf(acc + 1e-8f);
    }
}

// ---------------- weight rearrange: raw W -> broadcastable dup-float2 -------
// dst[ocb][chunk][ci][ky][og][jp][slot], slot = l*3 + kx (l = oc&1), pads 6,7.
__global__ void wrearrange_kernel(const float* __restrict__ W,
                                  float2* __restrict__ wr) {
    int e = blockIdx.x * 256 + threadIdx.x;   // 0 .. 589823
    int oc  = e / 2304;
    int rem = e - oc * 2304;
    int ci  = rem / 9;
    int tap = rem - ci * 9;
    int ky  = tap / 3, kx = tap - ky * 3;
    int ocb = oc >> 6, og = (oc >> 3) & 7, jp = (oc >> 1) & 3, l = oc & 1;
    int c = ci >> 3, cil = ci & 7;
    float w = __ldg(&W[e]);   // W is [oc][ci][ky][kx] contiguous == e
    size_t dst = (((((((size_t)ocb * 32 + c) * 8 + cil) * 3 + ky) * 8 + og) * 4 + jp) * 8)
                 + (size_t)(l * 3 + kx);
    wr[dst] = make_float2(w, w);
}

// ---------------- fused mod/demod 3x3 conv + noise + bias + leaky relu ------
// CTA: 64 out-channels x (16 rows x 32 cols) pixel tile. 512 threads.
// Thread: 8 oc x 8 px. Cin chunked by 8, double buffered.
#define CK        8
#define IN_PITCH  35
#define IN_FLOATS (CK * 18 * IN_PITCH)               // 5040
#define IN_TOT    (CK * 18 * 34)                     // 4896 staged elems
#define W_CHUNK_BYTES (CK * 3 * 8 * 4 * 8 * 8)       // 49152 B per chunk
#define SM_STYLE_OFF 0
#define SM_IN_OFF    1024
#define SM_W_OFF     (SM_IN_OFF + 2 * IN_FLOATS * 4) // 1024 + 40320 = 41344
#define CONV_SMEM    (SM_W_OFF + 2 * W_CHUNK_BYTES)  // + 98304 = 139648 B

__global__ __launch_bounds__(512, 1)
void conv3x3_mod_kernel(const float* __restrict__ in,
                        const float2* __restrict__ wr,    // rearranged weights
                        const float* __restrict__ style,  // [B,CH] (input ch)
                        const float* __restrict__ rsig,   // [B,CH] (out ch)
                        const float* __restrict__ bias,   // [CH]
                        const float* __restrict__ ns,     // [1]
                        const float* __restrict__ noise,  // [B,1,H,W]
                        float* __restrict__ outp) {
    extern __shared__ unsigned char smraw[];
    float* s_style = (float*)(smraw + SM_STYLE_OFF);
    float* s_in    = (float*)(smraw + SM_IN_OFF);            // [2][IN_FLOATS]
    unsigned char* s_w = smraw + SM_W_OFF;                   // [2][W_CHUNK_BYTES]

    const int tid = threadIdx.x;
    const int og  = tid >> 6;        // 0..7 (warp-constant)
    const int pg  = tid & 63;
    const int r   = pg >> 2;         // 0..15
    const int cg  = pg & 3;          // 0..3

    const int tilex = blockIdx.x;    // 0..3
    const int tiley = blockIdx.y;    // 0..7
    const int b     = blockIdx.z >> 2;
    const int ocb   = blockIdx.z & 3;   // 4 blocks of 64 oc

    const int y  = tiley * 16 + r;
    const int x0 = tilex * 32 + cg * 8;

    unsigned long long acc[8][4];
    #pragma unroll
    for (int j = 0; j < 8; j++)
        #pragma unroll
        for (int k = 0; k < 4; k++) acc[j][k] = 0ull;

    if (tid < CH) s_style[tid] = __ldg(&style[b * CH + tid]);

    float ipre[10];

    // prefetch input chunk c0n into registers (raw, style applied at store)
    auto prefetch_in = [&](int c0n) {
        #pragma unroll
        for (int i = 0; i < 10; i++) {
            int e = tid + 512 * i;
            if (e < IN_TOT) {
                int ci  = e / (18 * 34);
                int rem = e - ci * (18 * 34);
                int iy  = rem / 34;
                int ix  = rem - iy * 34;
                int gy = tiley * 16 - 1 + iy;
                int gx = tilex * 32 - 1 + ix;
                float v = 0.f;
                if ((unsigned)gy < (unsigned)HW && (unsigned)gx < (unsigned)HW)
                    v = __ldg(&in[((size_t)(b * CH + c0n + ci) << 14) + (gy << 7) + gx]);
                ipre[i] = v;
            }
        }
    };
    // store prefetched input (x style[ci]) into buffer p
    auto store_in = [&](int c0n, int p) {
        float* sin_p = s_in + p * IN_FLOATS;
        #pragma unroll
        for (int i = 0; i < 10; i++) {
            int e = tid + 512 * i;
            if (e < IN_TOT) {
                int ci  = e / (18 * 34);
                int rem = e - ci * (18 * 34);
                int iy  = rem / 34;
                int ix  = rem - iy * 34;
                sin_p[(ci * 18 + iy) * IN_PITCH + ix] = ipre[i] * s_style[c0n + ci];
            }
        }
    };
    // cp.async the rearranged weight chunk c (96B per thread) into buffer p
    auto stage_w = [&](int c, int p) {
        const unsigned char* src = (const unsigned char*)wr
            + ((size_t)(ocb * 32 + c)) * W_CHUNK_BYTES + (size_t)tid * 96;
        unsigned char* dst = s_w + p * W_CHUNK_BYTES + tid * 96;
        #pragma unroll
        for (int k = 0; k < 6; k++)
            cp_async16(dst + k * 16, src + k * 16);
        CP_COMMIT();
    };

    stage_w(0, 0);
    prefetch_in(0);
    __syncthreads();            // s_style visible
    store_in(0, 0);
    CP_WAIT0();
    __syncthreads();            // buffer 0 ready

    for (int c = 0; c < CH / CK; c++) {
        const int p = c & 1;
        if (c + 1 < CH / CK) {
            stage_w(c + 1, 1 - p);
            prefetch_in((c + 1) * CK);
        }

        const float* sin_p = s_in + p * IN_FLOATS;
        const unsigned char* sw_p = s_w + p * W_CHUNK_BYTES;
        #pragma unroll 1
        for (int ci = 0; ci < CK; ci++) {
            #pragma unroll
            for (int ky = 0; ky < 3; ky++) {
                const float* rowp = &sin_p[(ci * 18 + r + ky) * IN_PITCH + cg * 8];
                float xr[10];
                #pragma unroll
                for (int m = 0; m < 10; m++) xr[m] = rowp[m];
                unsigned long long ev[5], od[4];
                #pragma unroll
                for (int k2 = 0; k2 < 5; k2++) ev[k2] = pack2(xr[2*k2], xr[2*k2+1]);
                #pragma unroll
                for (int k2 = 0; k2 < 4; k2++) od[k2] = pack2(xr[2*k2+1], xr[2*k2+2]);
                const ulonglong2* wb = (const ulonglong2*)
                    (sw_p + ((ci * 3 + ky) * 8 + og) * 256);
                #pragma unroll
                for (int jp = 0; jp < 4; jp++) {
                    ulonglong2 qa = wb[jp * 4 + 0];   // slots 0,1
                    ulonglong2 qb = wb[jp * 4 + 1];   // slots 2,3
                    ulonglong2 qc = wb[jp * 4 + 2];   // slots 4,5
                    const int j0 = jp * 2, j1 = jp * 2 + 1;
                    #pragma unroll
                    for (int k = 0; k < 4; k++) {
                        acc[j0][k] = ffma2(ev[k],     qa.x, acc[j0][k]);
                        acc[j0][k] = ffma2(od[k],     qa.y, acc[j0][k]);
                        acc[j0][k] = ffma2(ev[k + 1], qb.x, acc[j0][k]);
                        acc[j1][k] = ffma2(ev[k],     qb.y, acc[j1][k]);
                        acc[j1][k] = ffma2(od[k],     qc.x, acc[j1][k]);
                        acc[j1][k] = ffma2(ev[k + 1], qc.y, acc[j1][k]);
                    }
                }
            }
        }

        if (c + 1 < CH / CK) store_in((c + 1) * CK, 1 - p);
        CP_WAIT0();
        __syncthreads();
    }

    // ---- epilogue: demod, noise, bias, leaky relu ----
    const float nsv = ns[0];
    float nz[8];
    {
        const float* np = noise + ((size_t)b << 14) + (y << 7) + x0;
        #pragma unroll
        for (int k = 0; k < 4; k++) {
            float2 t = *(const float2*)(np + 2 * k);
            nz[2*k] = t.x; nz[2*k+1] = t.y;
        }
    }
    #pragma unroll
    for (int j = 0; j < 8; j++) {
        const int oc = ocb * 64 + og * 8 + j;   // j = jp*2 + l
        const float rs = rsig[b * CH + oc];
        const float bj = bias[oc];
        float* op = outp + ((size_t)(b * CH + oc) << 14) + (y << 7) + x0;
        #pragma unroll
        for (int k = 0; k < 4; k++) {
            float v0, v1;
            unpack2(acc[j][k], v0, v1);
            v0 = v0 * rs + nsv * nz[2*k]     + bj;
            v1 = v1 * rs + nsv * nz[2*k + 1] + bj;
            v0 = (v0 > 0.f) ? v0 : 0.2f * v0;
            v1 = (v1 > 0.f) ? v1 : 0.2f * v1;
            *(float2*)(op + 2 * k) = make_float2(v0, v1);
        }
    }
}

// ---------------- RGB 1x1 modulated conv (no demod) ------------------------
__global__ void rgb_kernel(const float* __restrict__ out2,
                           const float* __restrict__ W3,      // [3,CH]
                           const float* __restrict__ style3,  // [B,CH]
                           float* __restrict__ rgb) {
    __shared__ float cf[3][CH];
    const int y = blockIdx.x;
    const int b = blockIdx.y;
    const int tid = threadIdx.x;
    for (int e = tid; e < 3 * CH; e += 128) {
        int rr = e >> 8;
        int o  = e & 255;
        cf[rr][o] = __ldg(&W3[rr * CH + o]) * style3[b * CH + o];
    }
    __syncthreads();
    const int x = tid;
    float a0 = 0.f, a1 = 0.f, a2 = 0.f;
    const float* base = out2 + ((size_t)(b * CH) << 14) + (y << 7) + x;
    #pragma unroll 8
    for (int o = 0; o < CH; o++) {
        float v = base[(size_t)o << 14];
        a0 += cf[0][o] * v;
        a1 += cf[1][o] * v;
        a2 += cf[2][o] * v;
    }
    const size_t px = ((size_t)y << 7) + x;
    rgb[((size_t)(b * 3 + 0) << 14) + px] = a0;
    rgb[((size_t)(b * 3 + 1) << 14) + px] = a1;
    rgb[((size_t)(b * 3 + 2) << 14) + px] = a2;
}

// ---------------------------------------------------------------------------
extern "C" void kernel_launch(void* const* d_in, const int* in_sizes, int n_in,
                              void* d_out, int out_size) {
    (void)in_sizes; (void)n_in; (void)out_size;
    const float* fm     = (const float*)d_in[0];
    const float* wv     = (const float*)d_in[1];
    const float* noise1 = (const float*)d_in[2];
    const float* noise2 = (const float*)d_in[3];
    const float* A1w    = (const float*)d_in[4];
    const float* A1b    = (const float*)d_in[5];
    const float* A2w    = (const float*)d_in[6];
    const float* A2b    = (const float*)d_in[7];
    const float* A3w    = (const float*)d_in[8];
    const float* A3b    = (const float*)d_in[9];
    const float* W1     = (const float*)d_in[10];
    const float* W2     = (const float*)d_in[11];
    const float* W3     = (const float*)d_in[12];
    const float* ns1    = (const float*)d_in[13];
    const float* ns2    = (const float*)d_in[14];
    const float* b1     = (const float*)d_in[15];
    const float* b2     = (const float*)d_in[16];

    float* out = (float*)d_out;                                   // [8,256,128,128]
    float* rgb = out + (size_t)BATCH * CH * HW * HW;              // [8,3,128,128]

    void *p_mid, *p_s1, *p_s2, *p_s3, *p_r1, *p_r2, *p_q1, *p_q2, *p_w1, *p_w2;
    cudaGetSymbolAddress(&p_mid, g_mid);
    cudaGetSymbolAddress(&p_s1, g_s1);
    cudaGetSymbolAddress(&p_s2, g_s2);
    cudaGetSymbolAddress(&p_s3, g_s3);
    cudaGetSymbolAddress(&p_r1, g_r1);
    cudaGetSymbolAddress(&p_r2, g_r2);
    cudaGetSymbolAddress(&p_q1, g_wq1);
    cudaGetSymbolAddress(&p_q2, g_wq2);
    cudaGetSymbolAddress(&p_w1, g_wr1);
    cudaGetSymbolAddress(&p_w2, g_wr2);
    float* mid = (float*)p_mid;
    float* s1 = (float*)p_s1; float* s2 = (float*)p_s2; float* s3 = (float*)p_s3;
    float* r1 = (float*)p_r1; float* r2 = (float*)p_r2;
    float* q1 = (float*)p_q1; float* q2 = (float*)p_q2;
    float2* wr1 = (float2*)p_w1; float2* wr2 = (float2*)p_w2;

    cudaFuncSetAttribute(conv3x3_mod_kernel,
                         cudaFuncAttributeMaxDynamicSharedMemorySize, CONV_SMEM);

    styles_kernel<<<dim3(CH / 8, BATCH), 256>>>(wv, A1w, A1b, s1);
    styles_kernel<<<dim3(CH / 8, BATCH), 256>>>(wv, A2w, A2b, s2);
    styles_kernel<<<dim3(CH / 8, BATCH), 256>>>(wv, A3w, A3b, s3);
    wsq_kernel<<<CH * CH / 256, 256>>>(W1, q1);
    wsq_kernel<<<CH * CH / 256, 256>>>(W2, q2);
    rsigma_kernel<<<dim3(BATCH, CH / 32), 256>>>(s1, q1, r1);
    rsigma_kernel<<<dim3(BATCH, CH / 32), 256>>>(s2, q2, r2);
    wrearrange_kernel<<<CH * CH * 9 / 256, 256>>>(W1, wr1);
    wrearrange_kernel<<<CH * CH * 9 / 256, 256>>>(W2, wr2);

    dim3 cgrid(4, 8, BATCH * 4);
    conv3x3_mod_kernel<<<cgrid, 512, CONV_SMEM>>>(fm,  wr1, s1, r1, b1, ns1, noise1, mid);
    conv3x3_mod_kernel<<<cgrid, 512, CONV_SMEM>>>(mid, wr2, s2, r2, b2, ns2, noise2, out);

    rgb_kernel<<<dim3(HW, BATCH), 128>>>(out, W3, s3, rgb);
}

// round 11
// speedup vs baseline: 3.6569x; 3.2436x over previous
#include <cuda_runtime.h>
#include <cuda_bf16.h>
#include <cstddef>
#include <cstdint>

// ---------------------------------------------------------------------------
// StyleGAN2 block via legacy tensor cores (mma.sync m16n8k16 bf16, base PTX).
// Conv as implicit GEMM: taps = shifted ldmatrix row addresses into one B slab.
// Precision: bf16 hi/lo split packed into K (Ah*Bh + Al*Bh + Ah*Bl), ~1e-5.
// R11 fixes vs R10: (1) B ldmatrix must be NON-trans for px-major rows;
// (2) A double-buffer race: stage next A only after the pre-MMA barrier.
// ---------------------------------------------------------------------------

#define BATCH 8
#define CH    256
#define HW    128
#define LAT   512

__device__ float g_mid[(size_t)BATCH * CH * HW * HW];   // conv1 output
__device__ float g_s1[BATCH * CH];
__device__ float g_s2[BATCH * CH];
__device__ float g_s3[BATCH * CH];
__device__ float g_r1[BATCH * CH];
__device__ float g_r2[BATCH * CH];
__device__ float g_wq1[CH * CH];
__device__ float g_wq2[CH * CH];
// rearranged weights: 96 stages x [kx(3)][oc(128)][40 slots] bf16  (2.95MB)
#define WA_STAGE_HALFS 15360            // 3*128*40
#define WA_HALFS ((size_t)96 * WA_STAGE_HALFS)
__device__ unsigned short g_wa1[WA_HALFS];
__device__ unsigned short g_wa2[WA_HALFS];

// ---------------- helpers ----------------
__device__ __forceinline__ float warp_sum(float v) {
    #pragma unroll
    for (int m = 16; m > 0; m >>= 1) v += __shfl_xor_sync(0xffffffffu, v, m);
    return v;
}
__device__ __forceinline__ uint32_t smem_u32(const void* p) {
    uint32_t a;
    asm("{ .reg .u64 t; cvta.to.shared.u64 t, %1; cvt.u32.u64 %0, t; }"
        : "=r"(a) : "l"(p));
    return a;
}
__device__ __forceinline__ void cp_async16(uint32_t smem, const void* gmem) {
    asm volatile("cp.async.cg.shared.global [%0], [%1], 16;" :: "r"(smem), "l"(gmem));
}
#define CP_COMMIT() asm volatile("cp.async.commit_group;" ::: "memory")
#define CP_WAIT0()  asm volatile("cp.async.wait_group 0;" ::: "memory")

#define LDM_X4(r, addr) \
    asm volatile("ldmatrix.sync.aligned.m8n8.x4.shared.b16 {%0,%1,%2,%3}, [%4];" \
        : "=r"((r)[0]), "=r"((r)[1]), "=r"((r)[2]), "=r"((r)[3]) : "r"(addr))
// NON-trans x2: rows addressed by lanes 0-15; lane l gets M[l/4][2*(l%4)..+1]
#define LDM_X2(r0, r1, addr) \
    asm volatile("ldmatrix.sync.aligned.m8n8.x2.shared.b16 {%0,%1}, [%2];" \
        : "=r"(r0), "=r"(r1) : "r"(addr))
#define MMA_BF16(c, a, b0, b1) \
    asm volatile("mma.sync.aligned.m16n8k16.row.col.f32.bf16.bf16.f32 " \
        "{%0,%1,%2,%3}, {%4,%5,%6,%7}, {%8,%9}, {%0,%1,%2,%3};" \
        : "+f"((c)[0]), "+f"((c)[1]), "+f"((c)[2]), "+f"((c)[3]) \
        : "r"((a)[0]), "r"((a)[1]), "r"((a)[2]), "r"((a)[3]), "r"(b0), "r"(b1))

// ---------------- small kernels ----------------
__global__ void styles_kernel(const float* __restrict__ wvec,
                              const float* __restrict__ Aw,
                              const float* __restrict__ Ab,
                              float* __restrict__ outp) {
    const int b = blockIdx.y, wid = threadIdx.x >> 5, lane = threadIdx.x & 31;
    const int o = blockIdx.x * 8 + wid;
    const float* wp = wvec + b * LAT;
    const float* ap = Aw + (size_t)o * LAT;
    float acc = 0.f;
    #pragma unroll
    for (int it = 0; it < LAT / 32; it++) {
        int k = lane + 32 * it;
        acc += __ldg(&wp[k]) * __ldg(&ap[k]);
    }
    acc = warp_sum(acc);
    if (lane == 0) outp[b * CH + o] = acc + __ldg(&Ab[o]);
}
__global__ void wsq_kernel(const float* __restrict__ W, float* __restrict__ wq) {
    const int oi = blockIdx.x * 256 + threadIdx.x;
    const float* wp = W + (size_t)oi * 9;
    float s = 0.f;
    #pragma unroll
    for (int t = 0; t < 9; t++) { float v = __ldg(&wp[t]); s += v * v; }
    wq[oi] = s;
}
__global__ void rsigma_kernel(const float* __restrict__ style,
                              const float* __restrict__ wq,
                              float* __restrict__ rsig) {
    __shared__ float ss[CH];
    const int b = blockIdx.x, tid = threadIdx.x, wid = tid >> 5, lane = tid & 31;
    { float s = style[b * CH + tid]; ss[tid] = s * s; }
    __syncthreads();
    const int o0 = blockIdx.y * 32 + wid * 4;
    #pragma unroll
    for (int j = 0; j < 4; j++) {
        const int o = o0 + j;
        const float* qp = wq + (size_t)o * CH;
        float acc = 0.f;
        #pragma unroll
        for (int it = 0; it < CH / 32; it++)
            acc += ss[lane + 32 * it] * __ldg(&qp[lane + 32 * it]);
        acc = warp_sum(acc);
        if (lane == 0) rsig[b * CH + o] = rsqrtf(acc + 1e-8f);
    }
}

// ---------------- weight prep: W[256,256,3,3] -> ldmatrix-ready hi/lo -------
// stage st = (ocb*16 + chunk)*3 + ky; layout [kx][oc(128)][40] bf16 (80B rows)
// slots [0,16): Wh(ci = chunk*16+s), [16,32): Wl, [32,40): pad.
__global__ void wprep_kernel(const float* __restrict__ W,
                             unsigned short* __restrict__ wa) {
    size_t e = (size_t)blockIdx.x * 256 + threadIdx.x;   // < 96*15360
    int st = (int)(e / WA_STAGE_HALFS);
    int r  = (int)(e - (size_t)st * WA_STAGE_HALFS);
    int kx = r / 5120;  r -= kx * 5120;
    int oc = r / 40;
    int slot = r - oc * 40;
    int ocb = st / 48, s2 = st - ocb * 48;
    int chunk = s2 / 3, ky = s2 - chunk * 3;
    unsigned short outv = 0;
    if (slot < 32) {
        int ci = chunk * 16 + (slot & 15);
        float w = __ldg(&W[((size_t)(ocb * 128 + oc) * CH + ci) * 9 + ky * 3 + kx]);
        __nv_bfloat16 wh = __float2bfloat16(w);
        if (slot < 16) outv = __bfloat16_as_ushort(wh);
        else outv = __bfloat16_as_ushort(__float2bfloat16(w - __bfloat162float(wh)));
    }
    wa[e] = outv;
}

// ---------------- tensor-core conv kernel -----------------------------------
// CTA: 128 oc x 256 px (2 image rows). 256 threads = 8 warps (warp 64x64).
// smem: [0,1024) style | [1024, 42624) B slab (520 rows x 80B) |
//       [42624, 104064) A double buffer (2 x 30720B)
#define SMB_OFF   1024
#define SMA_OFF   42624
#define A_STAGE   30720
#define CONV_SMEM 104064

__global__ __launch_bounds__(256, 1)
void conv_mma_kernel(const float* __restrict__ in,
                     const unsigned short* __restrict__ wa,
                     const float* __restrict__ style,
                     const float* __restrict__ rsig,
                     const float* __restrict__ bias,
                     const float* __restrict__ ns,
                     const float* __restrict__ noise,
                     float* __restrict__ outp) {
    extern __shared__ unsigned char sm[];
    float* s_style = (float*)sm;
    unsigned char* smB = sm + SMB_OFF;
    const uint32_t smBu = smem_u32(smB);
    const uint32_t smAu = smem_u32(sm + SMA_OFF);

    const int tid  = threadIdx.x;
    const int wid  = tid >> 5;
    const int lane = tid & 31;
    const int wm   = wid & 1;        // oc half
    const int wn   = wid >> 1;       // 0..3 -> (row, x-half)
    const int y0   = blockIdx.x * 2;
    const int ocb  = blockIdx.y;
    const int b    = blockIdx.z;

    if (tid < CH) s_style[tid] = __ldg(&style[b * CH + tid]);

    float acc[4][8][4];
    #pragma unroll
    for (int m = 0; m < 4; m++)
        #pragma unroll
        for (int n = 0; n < 8; n++)
            #pragma unroll
            for (int k = 0; k < 4; k++) acc[m][n][k] = 0.f;

    // lane-level ldmatrix address components
    // A (x4): lanes 0-15 -> oc rows, byte 0; lanes 16-31 -> same rows, byte 16
    const uint32_t aLane = (uint32_t)(wm * 64 + (lane & 15)) * 80 + ((lane >> 4) * 16);
    // B (x2 non-trans): lanes 0-7 -> px rows byte 0 (k 0-7); 8-15 -> byte 16 (k 8-15)
    const uint32_t bLane = (uint32_t)(lane & 7) * 80 + (((lane >> 3) & 1) * 16);

    const unsigned short* waBase = wa + (size_t)ocb * 48 * WA_STAGE_HALFS;

    auto stageA = [&](int st) {
        const unsigned char* src = (const unsigned char*)(waBase + (size_t)st * WA_STAGE_HALFS);
        uint32_t dst = smAu + (uint32_t)(st & 1) * A_STAGE;
        for (int i = tid; i < 1920; i += 256)
            cp_async16(dst + i * 16, src + (size_t)i * 16);
    };
    auto buildB = [&](int chunk) {
        for (int e = tid; e < 4160; e += 256) {
            int cl = e / 520;  int r = e - cl * 520;
            int rr = r / 130;  int pxi = r - rr * 130;
            int yi = y0 - 1 + rr, xi = pxi - 1;
            int ci = chunk * 16 + cl * 2;
            float v0 = 0.f, v1 = 0.f;
            if ((unsigned)yi < (unsigned)HW && (unsigned)xi < (unsigned)HW) {
                size_t base = ((size_t)(b * CH + ci) << 14) + (yi << 7) + xi;
                v0 = __ldg(&in[base]) * s_style[ci];
                v1 = __ldg(&in[base + (size_t)(1 << 14)]) * s_style[ci + 1];
            }
            __nv_bfloat16 h0 = __float2bfloat16(v0), h1 = __float2bfloat16(v1);
            __nv_bfloat16 l0 = __float2bfloat16(v0 - __bfloat162float(h0));
            __nv_bfloat16 l1 = __float2bfloat16(v1 - __bfloat162float(h1));
            uint32_t hh = ((uint32_t)__bfloat16_as_ushort(h1) << 16) | __bfloat16_as_ushort(h0);
            uint32_t ll = ((uint32_t)__bfloat16_as_ushort(l1) << 16) | __bfloat16_as_ushort(l0);
            int rp = rr * 130 + pxi;
            *(uint32_t*)(smB + rp * 80 + cl * 4)      = hh;   // k slots 2cl,2cl+1
            *(uint32_t*)(smB + rp * 80 + 32 + cl * 4) = ll;   // k slots 16+2cl,..
        }
    };

    stageA(0); CP_COMMIT();

    #pragma unroll 1
    for (int st = 0; st < 48; st++) {
        const int chunk = st / 3, ky = st - chunk * 3;
        if (ky == 0) { __syncthreads(); buildB(chunk); }   // all prior readers done
        CP_WAIT0();              // A(st) landed (only group in flight)
        __syncthreads();         // B(chunk) + A(st) visible; st-1 readers done
        if (st + 1 < 48) { stageA(st + 1); CP_COMMIT(); }  // safe: buffer free now

        const uint32_t aBuf = smAu + (uint32_t)(st & 1) * A_STAGE;
        const int rr  = (wn >> 1) + ky;       // B slab image-row
        const int x0w = (wn & 1) * 64;

        #pragma unroll 1
        for (int kx = 0; kx < 3; kx++) {
            uint32_t a0[4][4], a1[4][4];      // Ah frags, Al frags
            #pragma unroll
            for (int m = 0; m < 4; m++) {
                uint32_t aa = aBuf + (uint32_t)kx * 10240 + (uint32_t)m * (16 * 80) + aLane;
                LDM_X4(a0[m], aa);
                LDM_X4(a1[m], aa + 32);
            }
            const uint32_t bRow0 = smBu + (uint32_t)(rr * 130 + x0w + kx) * 80 + bLane;
            #pragma unroll
            for (int n = 0; n < 8; n++) {
                uint32_t ba = bRow0 + (uint32_t)n * (8 * 80);
                uint32_t bh0, bh1, bl0, bl1;
                LDM_X2(bh0, bh1, ba);         // Bh (k 0-15)
                LDM_X2(bl0, bl1, ba + 32);    // Bl (k 0-15 of lo slots)
                #pragma unroll
                for (int m = 0; m < 4; m++) MMA_BF16(acc[m][n], a0[m], bh0, bh1);
                #pragma unroll
                for (int m = 0; m < 4; m++) MMA_BF16(acc[m][n], a1[m], bh0, bh1);
                #pragma unroll
                for (int m = 0; m < 4; m++) MMA_BF16(acc[m][n], a0[m], bl0, bl1);
            }
        }
    }

    // ---- epilogue: demod + noise + bias + leaky relu ----
    const float nsv = __ldg(&ns[0]);
    const int y = y0 + (wn >> 1);
    #pragma unroll
    for (int m = 0; m < 4; m++) {
        const int oc0 = ocb * 128 + wm * 64 + m * 16 + (lane >> 2);
        const float rs0 = __ldg(&rsig[b * CH + oc0]);
        const float rs1 = __ldg(&rsig[b * CH + oc0 + 8]);
        const float bj0 = __ldg(&bias[oc0]);
        const float bj1 = __ldg(&bias[oc0 + 8]);
        float* op0 = outp + ((size_t)(b * CH + oc0) << 14) + (y << 7);
        float* op1 = op0 + ((size_t)8 << 14);
        #pragma unroll
        for (int n = 0; n < 8; n++) {
            const int x = (wn & 1) * 64 + n * 8 + 2 * (lane & 3);
            float2 nz = *(const float2*)(noise + ((size_t)b << 14) + (y << 7) + x);
            float v0 = acc[m][n][0] * rs0 + nsv * nz.x + bj0;
            float v1 = acc[m][n][1] * rs0 + nsv * nz.y + bj0;
            float v2 = acc[m][n][2] * rs1 + nsv * nz.x + bj1;
            float v3 = acc[m][n][3] * rs1 + nsv * nz.y + bj1;
            v0 = (v0 > 0.f) ? v0 : 0.2f * v0;
            v1 = (v1 > 0.f) ? v1 : 0.2f * v1;
            v2 = (v2 > 0.f) ? v2 : 0.2f * v2;
            v3 = (v3 > 0.f) ? v3 : 0.2f * v3;
            *(float2*)(op0 + x) = make_float2(v0, v1);
            *(float2*)(op1 + x) = make_float2(v2, v3);
        }
    }
}

// ---------------- RGB 1x1 modulated conv (no demod) ------------------------
__global__ void rgb_kernel(const float* __restrict__ out2,
                           const float* __restrict__ W3,
                           const float* __restrict__ style3,
                           float* __restrict__ rgb) {
    __shared__ float cf[3][CH];
    const int y = blockIdx.x, b = blockIdx.y, tid = threadIdx.x;
    for (int e = tid; e < 3 * CH; e += 128) {
        int rr = e >> 8, o = e & 255;
        cf[rr][o] = __ldg(&W3[rr * CH + o]) * style3[b * CH + o];
    }
    __syncthreads();
    const int x = tid;
    float a0 = 0.f, a1 = 0.f, a2 = 0.f;
    const float* base = out2 + ((size_t)(b * CH) << 14) + (y << 7) + x;
    #pragma unroll 8
    for (int o = 0; o < CH; o++) {
        float v = base[(size_t)o << 14];
        a0 += cf[0][o] * v; a1 += cf[1][o] * v; a2 += cf[2][o] * v;
    }
    const size_t px = ((size_t)y << 7) + x;
    rgb[((size_t)(b * 3 + 0) << 14) + px] = a0;
    rgb[((size_t)(b * 3 + 1) << 14) + px] = a1;
    rgb[((size_t)(b * 3 + 2) << 14) + px] = a2;
}

// ---------------------------------------------------------------------------
extern "C" void kernel_launch(void* const* d_in, const int* in_sizes, int n_in,
                              void* d_out, int out_size) {
    (void)in_sizes; (void)n_in; (void)out_size;
    const float* fm     = (const float*)d_in[0];
    const float* wv     = (const float*)d_in[1];
    const float* noise1 = (const float*)d_in[2];
    const float* noise2 = (const float*)d_in[3];
    const float* A1w    = (const float*)d_in[4];
    const float* A1b    = (const float*)d_in[5];
    const float* A2w    = (const float*)d_in[6];
    const float* A2b    = (const float*)d_in[7];
    const float* A3w    = (const float*)d_in[8];
    const float* A3b    = (const float*)d_in[9];
    const float* W1     = (const float*)d_in[10];
    const float* W2     = (const float*)d_in[11];
    const float* W3     = (const float*)d_in[12];
    const float* ns1    = (const float*)d_in[13];
    const float* ns2    = (const float*)d_in[14];
    const float* b1     = (const float*)d_in[15];
    const float* b2     = (const float*)d_in[16];

    float* out = (float*)d_out;
    float* rgb = out + (size_t)BATCH * CH * HW * HW;

    void *p_mid,*p_s1,*p_s2,*p_s3,*p_r1,*p_r2,*p_q1,*p_q2,*p_a1,*p_a2;
    cudaGetSymbolAddress(&p_mid, g_mid);
    cudaGetSymbolAddress(&p_s1, g_s1);
    cudaGetSymbolAddress(&p_s2, g_s2);
    cudaGetSymbolAddress(&p_s3, g_s3);
    cudaGetSymbolAddress(&p_r1, g_r1);
    cudaGetSymbolAddress(&p_r2, g_r2);
    cudaGetSymbolAddress(&p_q1, g_wq1);
    cudaGetSymbolAddress(&p_q2, g_wq2);
    cudaGetSymbolAddress(&p_a1, g_wa1);
    cudaGetSymbolAddress(&p_a2, g_wa2);
    float* mid = (float*)p_mid;
    float* s1 = (float*)p_s1; float* s2 = (float*)p_s2; float* s3 = (float*)p_s3;
    float* r1 = (float*)p_r1; float* r2 = (float*)p_r2;
    float* q1 = (float*)p_q1; float* q2 = (float*)p_q2;
    unsigned short* wa1 = (unsigned short*)p_a1;
    unsigned short* wa2 = (unsigned short*)p_a2;

    cudaFuncSetAttribute(conv_mma_kernel,
                         cudaFuncAttributeMaxDynamicSharedMemorySize, CONV_SMEM);

    styles_kernel<<<dim3(CH / 8, BATCH), 256>>>(wv, A1w, A1b, s1);
    styles_kernel<<<dim3(CH / 8, BATCH), 256>>>(wv, A2w, A2b, s2);
    styles_kernel<<<dim3(CH / 8, BATCH), 256>>>(wv, A3w, A3b, s3);
    wsq_kernel<<<CH * CH / 256, 256>>>(W1, q1);
    wsq_kernel<<<CH * CH / 256, 256>>>(W2, q2);
    rsigma_kernel<<<dim3(BATCH, CH / 32), 256>>>(s1, q1, r1);
    rsigma_kernel<<<dim3(BATCH, CH / 32), 256>>>(s2, q2, r2);
    wprep_kernel<<<(int)(WA_HALFS / 256), 256>>>(W1, wa1);
    wprep_kernel<<<(int)(WA_HALFS / 256), 256>>>(W2, wa2);

    dim3 cgrid(HW / 2, 2, BATCH);   // 64 row-pairs, 2 oc halves, 8 batches
    conv_mma_kernel<<<cgrid, 256, CONV_SMEM>>>(fm,  wa1, s1, r1, b1, ns1, noise1, mid);
    conv_mma_kernel<<<cgrid, 256, CONV_SMEM>>>(mid, wa2, s2, r2, b2, ns2, noise2, out);

    rgb_kernel<<<dim3(HW, BATCH), 128>>>(out, W3, s3, rgb);
}